// round 14
// baseline (speedup 1.0000x reference)
#include <cuda_runtime.h>
#include <cuda_bf16.h>

#define ZD 21
#define YD 256
#define XD 256
#define CIN 16
#define C1 32
#define C2 64
#define BN_EPS 1e-3f
#define GRID_SZ (2 * ZD * YD * XD)   // 2,752,512
#define NMAX 400000
#define FULLW 0xffffffffu
#define ROWVALID 64        // mask bit: this row exists
#define SENT 0xffffffffu   // queue sentinel: k-field = 8191, never matches

__device__ int      g_grid[GRID_SZ];
__device__ float    g_f1[NMAX * C1];
__device__ unsigned g_rb[27 * NMAX];   // slot-major: rb[e*NMAX + row] (layer-2 only)
__device__ int      g_cnt[NMAX];

__device__ __forceinline__ void prefetchL1(const void* p) {
    asm volatile("prefetch.global.L1 [%0];" :: "l"(p));
}

// ---------------------------------------------------------------------------
// Hash-grid build
// ---------------------------------------------------------------------------
__global__ void fill_grid_kernel() {
    int i = blockIdx.x * blockDim.x + threadIdx.x;
    if (i < GRID_SZ / 4) {
        ((int4*)g_grid)[i] = make_int4(-1, -1, -1, -1);
    }
}

__global__ void scatter_kernel(const int* __restrict__ coors, int n) {
    int i = blockIdx.x * blockDim.x + threadIdx.x;
    if (i < n) {
        int4 c = ((const int4*)coors)[i];  // (b, z, y, x)
        int lin = ((c.x * ZD + c.y) * YD + c.z) * XD + c.w;
        g_grid[lin] = i;
    }
}

// ---------------------------------------------------------------------------
// Probe helpers
// ---------------------------------------------------------------------------
__device__ __forceinline__ int probe2(int k, int lin, int msk) {
    int jz = k / 9, jy = (k / 3) % 3, jx = k % 3;
    int req = ((jy == 0) ? 1 : 0) | ((jx == 0) ? 2 : 0) | ROWVALID;
    int koff = (jz * YD + jy) * XD + jx;
    return ((msk & req) == req) ? __ldg(&g_grid[lin + koff]) : -1;
}

// ---------------------------------------------------------------------------
// Layer-2 rulebook: one thread per output row; 27 independent probes, then
// compact k-ascending entries (k<<19 | irow) into slot-major g_rb.
// ---------------------------------------------------------------------------
__global__ void rb2_build_kernel(const int* __restrict__ ocoors, int m) {
    int row = blockIdx.x * blockDim.x + threadIdx.x;
    if (row >= m) return;
    int4 c = ((const int4*)ocoors)[row];  // (b, oz, oy, ox)
    int z0 = c.y * 2;
    int y0 = c.z * 2 - 1;
    int x0 = c.w * 2 - 1;
    int lin = ((c.x * ZD + z0) * YD + y0) * XD + x0;   // may be < 0; probes guard
    int msk = (c.z > 0) | ((c.w > 0) << 1) | ROWVALID;
    int idx[27];
    #pragma unroll
    for (int k = 0; k < 27; k++) idx[k] = probe2(k, lin, msk);
    int cnt = 0;
    #pragma unroll
    for (int k = 0; k < 27; k++) {
        if (idx[k] >= 0) g_rb[(cnt++) * NMAX + row] = ((unsigned)k << 19) | (unsigned)idx[k];
    }
    g_cnt[row] = cnt;
}

extern __shared__ float smw[];

#define CONV2_W_ELEMS (27 * 32 * 32)

// ---------------------------------------------------------------------------
// Layer 1: SubMConv3d k=3 pad=1, CIN=16 -> C1=32, fused BN+ReLU
// (R10 measured-best form — unchanged.) 512 thr = 16 warps, 2 blocks/SM.
// ---------------------------------------------------------------------------
__global__ __launch_bounds__(512, 2) void conv1_kernel(
    const float* __restrict__ feat, const int* __restrict__ coors,
    const float* __restrict__ W1,
    const float* __restrict__ g1, const float* __restrict__ b1,
    const float* __restrict__ m1, const float* __restrict__ v1,
    int n)
{
    for (int e = threadIdx.x; e < 27 * CIN * C1; e += blockDim.x) {
        int k   = e / (CIN * C1);
        int rem = e % (CIN * C1);
        int ci  = rem / C1;
        int co  = rem % C1;
        int chunk = ci >> 2, pos = ci & 3;
        int sch = chunk ^ (co & 7);
        smw[(k * 32 + co) * 32 + sch * 4 + pos] = W1[e];
    }
    __syncthreads();

    int warp = threadIdx.x >> 5;
    int lane = threadIdx.x & 31;
    int row0 = blockIdx.x * 256 + warp * 16;

    int lin = 0, msk = 0;
    if (lane < 16) {
        int r = row0 + lane;
        if (r < n) {
            int4 c = ((const int4*)coors)[r];  // (b, z, y, x)
            lin = ((c.x * ZD + c.y) * YD + c.z) * XD + c.w;
            msk = (c.y > 0)             |
                  ((c.y < ZD - 1) << 1) |
                  ((c.z > 0)      << 2) |
                  ((c.z < YD - 1) << 3) |
                  ((c.w > 0)      << 4) |
                  ((c.w < XD - 1) << 5) |
                  ROWVALID;
        }
    }

    float acc[16];
    #pragma unroll
    for (int r = 0; r < 16; r++) acc[r] = 0.f;

    const float4* feat4 = (const float4*)feat;
    int swz = (lane & 7) * 4;

    int cur;
    {
        int req = 1 | 4 | 16 | ROWVALID;              // k=0: dz,dy,dx = -1
        int koff = (-1 * YD - 1) * XD - 1;
        cur = ((msk & req) == req) ? __ldg(&g_grid[lin + koff]) : -1;
        if (cur >= 0) prefetchL1(&feat4[cur * 4]);
    }
    int k = 0;
    #pragma unroll 1
    for (int dz = -1; dz <= 1; dz++) {
        #pragma unroll 1
        for (int dy = -1; dy <= 1; dy++) {
            #pragma unroll 1
            for (int dx = -1; dx <= 1; dx++, k++) {
                int nxt = -1;
                if (k < 26) {
                    int k1 = k + 1;
                    int dz1 = k1 / 9 - 1, dy1 = (k1 / 3) % 3 - 1, dx1 = k1 % 3 - 1;
                    int req1 = ((dz1 < 0) ? 1 : 0) | ((dz1 > 0) ? 2 : 0) |
                               ((dy1 < 0) ? 4 : 0) | ((dy1 > 0) ? 8 : 0) |
                               ((dx1 < 0) ? 16 : 0) | ((dx1 > 0) ? 32 : 0) | ROWVALID;
                    int koff1 = (dz1 * YD + dy1) * XD + dx1;
                    nxt = ((msk & req1) == req1) ? __ldg(&g_grid[lin + koff1]) : -1;
                    if (nxt >= 0) prefetchL1(&feat4[nxt * 4]);
                }
                unsigned mask = __ballot_sync(FULLW, cur >= 0) & 0xffffu;
                if (mask) {
                    const float* wrow = &smw[(k * 32 + lane) * 32];
                    float4 w0 = *(const float4*)&wrow[(0 * 4) ^ swz];
                    float4 w1 = *(const float4*)&wrow[(1 * 4) ^ swz];
                    float4 w2 = *(const float4*)&wrow[(2 * 4) ^ swz];
                    float4 w3 = *(const float4*)&wrow[(3 * 4) ^ swz];
                    #pragma unroll
                    for (int r = 0; r < 16; r++) {
                        if ((mask >> r) & 1) {   // warp-uniform
                            int idx = __shfl_sync(FULLW, cur, r);
                            const float4* fp = &feat4[idx * 4];
                            float4 f0 = __ldg(fp + 0);
                            float4 f1 = __ldg(fp + 1);
                            float4 f2 = __ldg(fp + 2);
                            float4 f3 = __ldg(fp + 3);
                            float a = acc[r];
                            a = fmaf(f0.x, w0.x, a); a = fmaf(f0.y, w0.y, a);
                            a = fmaf(f0.z, w0.z, a); a = fmaf(f0.w, w0.w, a);
                            a = fmaf(f1.x, w1.x, a); a = fmaf(f1.y, w1.y, a);
                            a = fmaf(f1.z, w1.z, a); a = fmaf(f1.w, w1.w, a);
                            a = fmaf(f2.x, w2.x, a); a = fmaf(f2.y, w2.y, a);
                            a = fmaf(f2.z, w2.z, a); a = fmaf(f2.w, w2.w, a);
                            a = fmaf(f3.x, w3.x, a); a = fmaf(f3.y, w3.y, a);
                            a = fmaf(f3.z, w3.z, a); a = fmaf(f3.w, w3.w, a);
                            acc[r] = a;
                        }
                    }
                }
                cur = nxt;
            }
        }
    }

    float s  = g1[lane] * rsqrtf(v1[lane] + BN_EPS);
    float sh = b1[lane] - m1[lane] * s;
    #pragma unroll
    for (int r = 0; r < 16; r++) {
        int row = row0 + r;
        if (row < n) {
            float o = fmaf(acc[r], s, sh);
            g_f1[row * C1 + lane] = o > 0.f ? o : 0.f;
        }
    }
}

// ---------------------------------------------------------------------------
// Layer 2: SparseConv3d C1=32 -> C2=64, fused BN+ReLU.
// Cout halves split ACROSS BLOCKS. 384 thr = 12 warps, 1 block/SM
// (smem = 110.6KB weights + 96KB smem accumulators = 206.6KB).
// Warp owns 64 ROWS via DUAL per-lane queues: A = base+lane, B = base+32+lane.
// Per k: one weight load serves pairs of BOTH row sets -> weight-LDS and
// per-k overhead amortized 2x. Pairs processed 2-way interleaved as before.
// ---------------------------------------------------------------------------
__global__ __launch_bounds__(384, 1) void conv2_kernel(
    const float* __restrict__ W2,
    const float* __restrict__ g2, const float* __restrict__ b2,
    const float* __restrict__ m2, const float* __restrict__ v2,
    float* __restrict__ out, int m)
{
    int half = blockIdx.x & 1;

    for (int e = threadIdx.x; e < CONV2_W_ELEMS; e += blockDim.x) {
        int k   = e / (C1 * 32);
        int rem = e % (C1 * 32);
        int ci  = rem / 32;
        int col = rem % 32;
        int chunk = ci >> 2, pos = ci & 3;
        int sch = chunk ^ (col & 7);
        smw[(k * 32 + col) * 32 + sch * 4 + pos] =
            W2[(k * C1 + ci) * C2 + half * 32 + col];
    }

    int warp = threadIdx.x >> 5;
    int lane = threadIdx.x & 31;

    // per-warp smem accumulator block: 64 rows x 32 couts
    float* sacc = smw + CONV2_W_ELEMS + warp * (64 * 32);
    #pragma unroll
    for (int r = 0; r < 64; r++) sacc[r * 32 + lane] = 0.f;
    __syncthreads();

    int base = (blockIdx.x >> 1) * 768 + warp * 64;
    int rowA = base + lane;
    int rowB = base + 32 + lane;

    const float4* f14 = (const float4*)g_f1;

    int cntA = (rowA < m) ? __ldg(&g_cnt[rowA]) : 0;
    int cntB = (rowB < m) ? __ldg(&g_cnt[rowB]) : 0;
    unsigned qa0 = (cntA > 0) ? __ldg(&g_rb[0 * NMAX + rowA]) : SENT;
    unsigned qa1 = (cntA > 1) ? __ldg(&g_rb[1 * NMAX + rowA]) : SENT;
    unsigned qa2 = (cntA > 2) ? __ldg(&g_rb[2 * NMAX + rowA]) : SENT;
    unsigned qa3 = (cntA > 3) ? __ldg(&g_rb[3 * NMAX + rowA]) : SENT;
    unsigned qa4 = (cntA > 4) ? __ldg(&g_rb[4 * NMAX + rowA]) : SENT;
    unsigned qa5 = (cntA > 5) ? __ldg(&g_rb[5 * NMAX + rowA]) : SENT;
    unsigned qa6 = (cntA > 6) ? __ldg(&g_rb[6 * NMAX + rowA]) : SENT;
    unsigned qa7 = (cntA > 7) ? __ldg(&g_rb[7 * NMAX + rowA]) : SENT;
    unsigned qb0 = (cntB > 0) ? __ldg(&g_rb[0 * NMAX + rowB]) : SENT;
    unsigned qb1 = (cntB > 1) ? __ldg(&g_rb[1 * NMAX + rowB]) : SENT;
    unsigned qb2 = (cntB > 2) ? __ldg(&g_rb[2 * NMAX + rowB]) : SENT;
    unsigned qb3 = (cntB > 3) ? __ldg(&g_rb[3 * NMAX + rowB]) : SENT;
    unsigned qb4 = (cntB > 4) ? __ldg(&g_rb[4 * NMAX + rowB]) : SENT;
    unsigned qb5 = (cntB > 5) ? __ldg(&g_rb[5 * NMAX + rowB]) : SENT;
    unsigned qb6 = (cntB > 6) ? __ldg(&g_rb[6 * NMAX + rowB]) : SENT;
    unsigned qb7 = (cntB > 7) ? __ldg(&g_rb[7 * NMAX + rowB]) : SENT;
    int eA = 8, eB = 8;

    if (qa0 != SENT) prefetchL1(&f14[(qa0 & 0x7FFFF) * 8]);
    if (qa1 != SENT) prefetchL1(&f14[(qa1 & 0x7FFFF) * 8]);
    if (qb0 != SENT) prefetchL1(&f14[(qb0 & 0x7FFFF) * 8]);
    if (qb1 != SENT) prefetchL1(&f14[(qb1 & 0x7FFFF) * 8]);

    int swz = (lane & 7) * 4;

    #pragma unroll 1
    for (int k = 0; k < 27; k++) {
        bool tA = ((qa0 >> 19) == (unsigned)k);
        bool tB = ((qb0 >> 19) == (unsigned)k);
        unsigned maskA = __ballot_sync(FULLW, tA);
        unsigned maskB = __ballot_sync(FULLW, tB);
        if (maskA | maskB) {
            const float* wrow = &smw[(k * 32 + lane) * 32];
            float4 w0 = *(const float4*)&wrow[(0 * 4) ^ swz];
            float4 w1 = *(const float4*)&wrow[(1 * 4) ^ swz];
            float4 w2 = *(const float4*)&wrow[(2 * 4) ^ swz];
            float4 w3 = *(const float4*)&wrow[(3 * 4) ^ swz];
            float4 w4 = *(const float4*)&wrow[(4 * 4) ^ swz];
            float4 w5 = *(const float4*)&wrow[(5 * 4) ^ swz];
            float4 w6 = *(const float4*)&wrow[(6 * 4) ^ swz];
            float4 w7 = *(const float4*)&wrow[(7 * 4) ^ swz];
            // process both row sets with the same register weights
            #pragma unroll 1
            for (int set = 0; set < 2; set++) {
                unsigned mm = set ? maskB : maskA;
                unsigned qh = set ? qb0 : qa0;
                int rbase = set ? 32 : 0;
                #pragma unroll 1
                while (mm) {
                    int j0 = __ffs(mm) - 1; mm &= mm - 1;
                    int j1 = -1;
                    if (mm) { j1 = __ffs(mm) - 1; mm &= mm - 1; }
                    int i0 = __shfl_sync(FULLW, (int)qh, j0) & 0x7FFFF;
                    int i1 = __shfl_sync(FULLW, (int)qh, (j1 >= 0) ? j1 : j0) & 0x7FFFF;
                    const float4* fp0 = &f14[i0 * 8];
                    const float4* fp1 = &f14[i1 * 8];
                    float4 a0 = __ldg(fp0 + 0), a1 = __ldg(fp0 + 1);
                    float4 a2 = __ldg(fp0 + 2), a3 = __ldg(fp0 + 3);
                    float4 a4 = __ldg(fp0 + 4), a5 = __ldg(fp0 + 5);
                    float4 a6 = __ldg(fp0 + 6), a7 = __ldg(fp0 + 7);
                    float4 b0, b1_, b2, b3, b4, b5, b6, b7;
                    if (j1 >= 0) {
                        b0 = __ldg(fp1 + 0); b1_ = __ldg(fp1 + 1);
                        b2 = __ldg(fp1 + 2); b3 = __ldg(fp1 + 3);
                        b4 = __ldg(fp1 + 4); b5 = __ldg(fp1 + 5);
                        b6 = __ldg(fp1 + 6); b7 = __ldg(fp1 + 7);
                    }
                    float r0 = 0.f;
                    r0 = fmaf(a0.x, w0.x, r0); r0 = fmaf(a0.y, w0.y, r0);
                    r0 = fmaf(a0.z, w0.z, r0); r0 = fmaf(a0.w, w0.w, r0);
                    r0 = fmaf(a1.x, w1.x, r0); r0 = fmaf(a1.y, w1.y, r0);
                    r0 = fmaf(a1.z, w1.z, r0); r0 = fmaf(a1.w, w1.w, r0);
                    r0 = fmaf(a2.x, w2.x, r0); r0 = fmaf(a2.y, w2.y, r0);
                    r0 = fmaf(a2.z, w2.z, r0); r0 = fmaf(a2.w, w2.w, r0);
                    r0 = fmaf(a3.x, w3.x, r0); r0 = fmaf(a3.y, w3.y, r0);
                    r0 = fmaf(a3.z, w3.z, r0); r0 = fmaf(a3.w, w3.w, r0);
                    r0 = fmaf(a4.x, w4.x, r0); r0 = fmaf(a4.y, w4.y, r0);
                    r0 = fmaf(a4.z, w4.z, r0); r0 = fmaf(a4.w, w4.w, r0);
                    r0 = fmaf(a5.x, w5.x, r0); r0 = fmaf(a5.y, w5.y, r0);
                    r0 = fmaf(a5.z, w5.z, r0); r0 = fmaf(a5.w, w5.w, r0);
                    r0 = fmaf(a6.x, w6.x, r0); r0 = fmaf(a6.y, w6.y, r0);
                    r0 = fmaf(a6.z, w6.z, r0); r0 = fmaf(a6.w, w6.w, r0);
                    r0 = fmaf(a7.x, w7.x, r0); r0 = fmaf(a7.y, w7.y, r0);
                    r0 = fmaf(a7.z, w7.z, r0); r0 = fmaf(a7.w, w7.w, r0);
                    sacc[(rbase + j0) * 32 + lane] += r0;
                    if (j1 >= 0) {
                        float r1 = 0.f;
                        r1 = fmaf(b0.x, w0.x, r1); r1 = fmaf(b0.y, w0.y, r1);
                        r1 = fmaf(b0.z, w0.z, r1); r1 = fmaf(b0.w, w0.w, r1);
                        r1 = fmaf(b1_.x, w1.x, r1); r1 = fmaf(b1_.y, w1.y, r1);
                        r1 = fmaf(b1_.z, w1.z, r1); r1 = fmaf(b1_.w, w1.w, r1);
                        r1 = fmaf(b2.x, w2.x, r1); r1 = fmaf(b2.y, w2.y, r1);
                        r1 = fmaf(b2.z, w2.z, r1); r1 = fmaf(b2.w, w2.w, r1);
                        r1 = fmaf(b3.x, w3.x, r1); r1 = fmaf(b3.y, w3.y, r1);
                        r1 = fmaf(b3.z, w3.z, r1); r1 = fmaf(b3.w, w3.w, r1);
                        r1 = fmaf(b4.x, w4.x, r1); r1 = fmaf(b4.y, w4.y, r1);
                        r1 = fmaf(b4.z, w4.z, r1); r1 = fmaf(b4.w, w4.w, r1);
                        r1 = fmaf(b5.x, w5.x, r1); r1 = fmaf(b5.y, w5.y, r1);
                        r1 = fmaf(b5.z, w5.z, r1); r1 = fmaf(b5.w, w5.w, r1);
                        r1 = fmaf(b6.x, w6.x, r1); r1 = fmaf(b6.y, w6.y, r1);
                        r1 = fmaf(b6.z, w6.z, r1); r1 = fmaf(b6.w, w6.w, r1);
                        r1 = fmaf(b7.x, w7.x, r1); r1 = fmaf(b7.y, w7.y, r1);
                        r1 = fmaf(b7.z, w7.z, r1); r1 = fmaf(b7.w, w7.w, r1);
                        sacc[(rbase + j1) * 32 + lane] += r1;
                    }
                }
            }
        }
        if (tA) {
            qa0 = qa1; qa1 = qa2; qa2 = qa3; qa3 = qa4;
            qa4 = qa5; qa5 = qa6; qa6 = qa7;
            qa7 = (eA < cntA) ? __ldg(&g_rb[eA * NMAX + rowA]) : SENT;
            eA++;
            if (qa1 != SENT) prefetchL1(&f14[(qa1 & 0x7FFFF) * 8]);
        }
        if (tB) {
            qb0 = qb1; qb1 = qb2; qb2 = qb3; qb3 = qb4;
            qb4 = qb5; qb5 = qb6; qb6 = qb7;
            qb7 = (eB < cntB) ? __ldg(&g_rb[eB * NMAX + rowB]) : SENT;
            eB++;
            if (qb1 != SENT) prefetchL1(&f14[(qb1 & 0x7FFFF) * 8]);
        }
    }

    int co = half * 32 + lane;
    float s  = g2[co] * rsqrtf(v2[co] + BN_EPS);
    float sh = b2[co] - m2[co] * s;
    #pragma unroll
    for (int r = 0; r < 64; r++) {
        int rr = base + r;
        if (rr < m) {
            float o = fmaf(sacc[r * 32 + lane], s, sh);
            out[rr * C2 + co] = o > 0.f ? o : 0.f;
        }
    }
}

// ---------------------------------------------------------------------------
// Tail: fill everything past f2 (out_coors as float, batch_size) if the
// harness flattened the full reference tuple into d_out.
// ---------------------------------------------------------------------------
__global__ void tail_kernel(const int* __restrict__ ocoors,
                            const int* __restrict__ bsz,
                            float* __restrict__ out, int m, int total)
{
    int i = blockIdx.x * blockDim.x + threadIdx.x + m * 64;
    if (i >= total) return;
    int j = i - m * 64;
    float v;
    if (j < m * 4)       v = (float)ocoors[j];
    else if (j == m * 4) v = (float)bsz[0];
    else                 v = 0.f;
    out[i] = v;
}

// ---------------------------------------------------------------------------
extern "C" void kernel_launch(void* const* d_in, const int* in_sizes, int n_in,
                              void* d_out, int out_size)
{
    const float* feat   = (const float*)d_in[0];
    const int*   coors  = (const int*)d_in[1];
    const int*   ocoors = (const int*)d_in[2];
    const float* W1     = (const float*)d_in[3];
    const float* g1     = (const float*)d_in[4];
    const float* b1     = (const float*)d_in[5];
    const float* m1     = (const float*)d_in[6];
    const float* v1     = (const float*)d_in[7];
    const float* W2     = (const float*)d_in[8];
    const float* g2     = (const float*)d_in[9];
    const float* b2     = (const float*)d_in[10];
    const float* m2     = (const float*)d_in[11];
    const float* v2     = (const float*)d_in[12];
    const int*   bsz    = (const int*)d_in[13];

    int n = in_sizes[0] / CIN;
    int m = in_sizes[2] / 4;

    fill_grid_kernel<<<(GRID_SZ / 4 + 255) / 256, 256>>>();
    scatter_kernel<<<(n + 255) / 256, 256>>>(coors, n);

    // layer 1 (R10 form: inline probes, register acc, 2 blocks/SM)
    int smem1 = 27 * C1 * 32 * (int)sizeof(float);   // 110,592 B
    cudaFuncSetAttribute(conv1_kernel, cudaFuncAttributeMaxDynamicSharedMemorySize, smem1);
    conv1_kernel<<<(n + 255) / 256, 512, smem1>>>(feat, coors, W1, g1, b1, m1, v1, n);

    // layer 2: rulebook, then conv with dual-queue 64-rows-per-warp
    rb2_build_kernel<<<(m + 255) / 256, 256>>>(ocoors, m);
    int smem2 = (CONV2_W_ELEMS + 12 * 64 * 32) * (int)sizeof(float);   // 206,848 B
    cudaFuncSetAttribute(conv2_kernel, cudaFuncAttributeMaxDynamicSharedMemorySize, smem2);
    int rowblocks = (m + 767) / 768;
    conv2_kernel<<<rowblocks * 2, 384, smem2>>>(W2, g2, b2, m2, v2, (float*)d_out, m);

    int tail = out_size - m * 64;
    if (tail > 0) {
        tail_kernel<<<(tail + 255) / 256, 256>>>(ocoors, bsz, (float*)d_out, m, out_size);
    }
}

// round 15
// speedup vs baseline: 1.0003x; 1.0003x over previous
#include <cuda_runtime.h>
#include <cuda_bf16.h>

#define ZD 21
#define YD 256
#define XD 256
#define CIN 16
#define C1 32
#define C2 64
#define BN_EPS 1e-3f
#define GRID_SZ (2 * ZD * YD * XD)   // 2,752,512
#define NMAX 400000
#define FULLW 0xffffffffu
#define ROWVALID 64        // mask bit: this row exists
#define SENT 0xffffffffu   // queue sentinel: k-field = 8191, never matches

__device__ int      g_grid[GRID_SZ];
__device__ float    g_f1[NMAX * C1];
__device__ unsigned g_rb[27 * NMAX];   // slot-major: rb[e*NMAX + row] (layer-2 only)
__device__ int      g_cnt[NMAX];

__device__ __forceinline__ void prefetchL1(const void* p) {
    asm volatile("prefetch.global.L1 [%0];" :: "l"(p));
}

// ---------------------------------------------------------------------------
// Hash-grid build
// ---------------------------------------------------------------------------
__global__ void fill_grid_kernel() {
    int i = blockIdx.x * blockDim.x + threadIdx.x;
    if (i < GRID_SZ / 4) {
        ((int4*)g_grid)[i] = make_int4(-1, -1, -1, -1);
    }
}

__global__ void scatter_kernel(const int* __restrict__ coors, int n) {
    int i = blockIdx.x * blockDim.x + threadIdx.x;
    if (i < n) {
        int4 c = ((const int4*)coors)[i];  // (b, z, y, x)
        int lin = ((c.x * ZD + c.y) * YD + c.z) * XD + c.w;
        g_grid[lin] = i;
    }
}

// ---------------------------------------------------------------------------
// Probe helpers
// ---------------------------------------------------------------------------
__device__ __forceinline__ int probe2(int k, int lin, int msk) {
    int jz = k / 9, jy = (k / 3) % 3, jx = k % 3;
    int req = ((jy == 0) ? 1 : 0) | ((jx == 0) ? 2 : 0) | ROWVALID;
    int koff = (jz * YD + jy) * XD + jx;
    return ((msk & req) == req) ? __ldg(&g_grid[lin + koff]) : -1;
}

// ---------------------------------------------------------------------------
// Layer-2 rulebook: one thread per output row; 27 independent probes, then
// compact k-ascending entries (k<<19 | irow) into slot-major g_rb.
// ---------------------------------------------------------------------------
__global__ void rb2_build_kernel(const int* __restrict__ ocoors, int m) {
    int row = blockIdx.x * blockDim.x + threadIdx.x;
    if (row >= m) return;
    int4 c = ((const int4*)ocoors)[row];  // (b, oz, oy, ox)
    int z0 = c.y * 2;
    int y0 = c.z * 2 - 1;
    int x0 = c.w * 2 - 1;
    int lin = ((c.x * ZD + z0) * YD + y0) * XD + x0;   // may be < 0; probes guard
    int msk = (c.z > 0) | ((c.w > 0) << 1) | ROWVALID;
    int idx[27];
    #pragma unroll
    for (int k = 0; k < 27; k++) idx[k] = probe2(k, lin, msk);
    int cnt = 0;
    #pragma unroll
    for (int k = 0; k < 27; k++) {
        if (idx[k] >= 0) g_rb[(cnt++) * NMAX + row] = ((unsigned)k << 19) | (unsigned)idx[k];
    }
    g_cnt[row] = cnt;
}

extern __shared__ float smw[];

#define CONV2_W_ELEMS (27 * 32 * 32)

// ---------------------------------------------------------------------------
// Layer 1: SubMConv3d k=3 pad=1, CIN=16 -> C1=32, fused BN+ReLU
// (R10 measured-best form — unchanged.) 512 thr = 16 warps, 2 blocks/SM.
// ---------------------------------------------------------------------------
__global__ __launch_bounds__(512, 2) void conv1_kernel(
    const float* __restrict__ feat, const int* __restrict__ coors,
    const float* __restrict__ W1,
    const float* __restrict__ g1, const float* __restrict__ b1,
    const float* __restrict__ m1, const float* __restrict__ v1,
    int n)
{
    for (int e = threadIdx.x; e < 27 * CIN * C1; e += blockDim.x) {
        int k   = e / (CIN * C1);
        int rem = e % (CIN * C1);
        int ci  = rem / C1;
        int co  = rem % C1;
        int chunk = ci >> 2, pos = ci & 3;
        int sch = chunk ^ (co & 7);
        smw[(k * 32 + co) * 32 + sch * 4 + pos] = W1[e];
    }
    __syncthreads();

    int warp = threadIdx.x >> 5;
    int lane = threadIdx.x & 31;
    int row0 = blockIdx.x * 256 + warp * 16;

    int lin = 0, msk = 0;
    if (lane < 16) {
        int r = row0 + lane;
        if (r < n) {
            int4 c = ((const int4*)coors)[r];  // (b, z, y, x)
            lin = ((c.x * ZD + c.y) * YD + c.z) * XD + c.w;
            msk = (c.y > 0)             |
                  ((c.y < ZD - 1) << 1) |
                  ((c.z > 0)      << 2) |
                  ((c.z < YD - 1) << 3) |
                  ((c.w > 0)      << 4) |
                  ((c.w < XD - 1) << 5) |
                  ROWVALID;
        }
    }

    float acc[16];
    #pragma unroll
    for (int r = 0; r < 16; r++) acc[r] = 0.f;

    const float4* feat4 = (const float4*)feat;
    int swz = (lane & 7) * 4;

    int cur;
    {
        int req = 1 | 4 | 16 | ROWVALID;              // k=0: dz,dy,dx = -1
        int koff = (-1 * YD - 1) * XD - 1;
        cur = ((msk & req) == req) ? __ldg(&g_grid[lin + koff]) : -1;
        if (cur >= 0) prefetchL1(&feat4[cur * 4]);
    }
    int k = 0;
    #pragma unroll 1
    for (int dz = -1; dz <= 1; dz++) {
        #pragma unroll 1
        for (int dy = -1; dy <= 1; dy++) {
            #pragma unroll 1
            for (int dx = -1; dx <= 1; dx++, k++) {
                int nxt = -1;
                if (k < 26) {
                    int k1 = k + 1;
                    int dz1 = k1 / 9 - 1, dy1 = (k1 / 3) % 3 - 1, dx1 = k1 % 3 - 1;
                    int req1 = ((dz1 < 0) ? 1 : 0) | ((dz1 > 0) ? 2 : 0) |
                               ((dy1 < 0) ? 4 : 0) | ((dy1 > 0) ? 8 : 0) |
                               ((dx1 < 0) ? 16 : 0) | ((dx1 > 0) ? 32 : 0) | ROWVALID;
                    int koff1 = (dz1 * YD + dy1) * XD + dx1;
                    nxt = ((msk & req1) == req1) ? __ldg(&g_grid[lin + koff1]) : -1;
                    if (nxt >= 0) prefetchL1(&feat4[nxt * 4]);
                }
                unsigned mask = __ballot_sync(FULLW, cur >= 0) & 0xffffu;
                if (mask) {
                    const float* wrow = &smw[(k * 32 + lane) * 32];
                    float4 w0 = *(const float4*)&wrow[(0 * 4) ^ swz];
                    float4 w1 = *(const float4*)&wrow[(1 * 4) ^ swz];
                    float4 w2 = *(const float4*)&wrow[(2 * 4) ^ swz];
                    float4 w3 = *(const float4*)&wrow[(3 * 4) ^ swz];
                    #pragma unroll
                    for (int r = 0; r < 16; r++) {
                        if ((mask >> r) & 1) {   // warp-uniform
                            int idx = __shfl_sync(FULLW, cur, r);
                            const float4* fp = &feat4[idx * 4];
                            float4 f0 = __ldg(fp + 0);
                            float4 f1 = __ldg(fp + 1);
                            float4 f2 = __ldg(fp + 2);
                            float4 f3 = __ldg(fp + 3);
                            float a = acc[r];
                            a = fmaf(f0.x, w0.x, a); a = fmaf(f0.y, w0.y, a);
                            a = fmaf(f0.z, w0.z, a); a = fmaf(f0.w, w0.w, a);
                            a = fmaf(f1.x, w1.x, a); a = fmaf(f1.y, w1.y, a);
                            a = fmaf(f1.z, w1.z, a); a = fmaf(f1.w, w1.w, a);
                            a = fmaf(f2.x, w2.x, a); a = fmaf(f2.y, w2.y, a);
                            a = fmaf(f2.z, w2.z, a); a = fmaf(f2.w, w2.w, a);
                            a = fmaf(f3.x, w3.x, a); a = fmaf(f3.y, w3.y, a);
                            a = fmaf(f3.z, w3.z, a); a = fmaf(f3.w, w3.w, a);
                            acc[r] = a;
                        }
                    }
                }
                cur = nxt;
            }
        }
    }

    float s  = g1[lane] * rsqrtf(v1[lane] + BN_EPS);
    float sh = b1[lane] - m1[lane] * s;
    #pragma unroll
    for (int r = 0; r < 16; r++) {
        int row = row0 + r;
        if (row < n) {
            float o = fmaf(acc[r], s, sh);
            g_f1[row * C1 + lane] = o > 0.f ? o : 0.f;
        }
    }
}

// ---------------------------------------------------------------------------
// Layer 2: SparseConv3d C1=32 -> C2=64, fused BN+ReLU.
// Cout halves split ACROSS BLOCKS. 384 thr = 12 warps, 1 block/SM
// (smem = 110.6KB weights + 96KB smem accumulators = 206.6KB).
// Warp owns 64 ROWS via DUAL per-lane queues: A = base+lane, B = base+32+lane.
// Per k: one weight load serves pairs of BOTH row sets -> weight-LDS and
// per-k overhead amortized 2x. Pairs processed 2-way interleaved as before.
// ---------------------------------------------------------------------------
__global__ __launch_bounds__(384, 1) void conv2_kernel(
    const float* __restrict__ W2,
    const float* __restrict__ g2, const float* __restrict__ b2,
    const float* __restrict__ m2, const float* __restrict__ v2,
    float* __restrict__ out, int m)
{
    int half = blockIdx.x & 1;

    for (int e = threadIdx.x; e < CONV2_W_ELEMS; e += blockDim.x) {
        int k   = e / (C1 * 32);
        int rem = e % (C1 * 32);
        int ci  = rem / 32;
        int col = rem % 32;
        int chunk = ci >> 2, pos = ci & 3;
        int sch = chunk ^ (col & 7);
        smw[(k * 32 + col) * 32 + sch * 4 + pos] =
            W2[(k * C1 + ci) * C2 + half * 32 + col];
    }

    int warp = threadIdx.x >> 5;
    int lane = threadIdx.x & 31;

    // per-warp smem accumulator block: 64 rows x 32 couts
    float* sacc = smw + CONV2_W_ELEMS + warp * (64 * 32);
    #pragma unroll
    for (int r = 0; r < 64; r++) sacc[r * 32 + lane] = 0.f;
    __syncthreads();

    int base = (blockIdx.x >> 1) * 768 + warp * 64;
    int rowA = base + lane;
    int rowB = base + 32 + lane;

    const float4* f14 = (const float4*)g_f1;

    int cntA = (rowA < m) ? __ldg(&g_cnt[rowA]) : 0;
    int cntB = (rowB < m) ? __ldg(&g_cnt[rowB]) : 0;
    unsigned qa0 = (cntA > 0) ? __ldg(&g_rb[0 * NMAX + rowA]) : SENT;
    unsigned qa1 = (cntA > 1) ? __ldg(&g_rb[1 * NMAX + rowA]) : SENT;
    unsigned qa2 = (cntA > 2) ? __ldg(&g_rb[2 * NMAX + rowA]) : SENT;
    unsigned qa3 = (cntA > 3) ? __ldg(&g_rb[3 * NMAX + rowA]) : SENT;
    unsigned qa4 = (cntA > 4) ? __ldg(&g_rb[4 * NMAX + rowA]) : SENT;
    unsigned qa5 = (cntA > 5) ? __ldg(&g_rb[5 * NMAX + rowA]) : SENT;
    unsigned qa6 = (cntA > 6) ? __ldg(&g_rb[6 * NMAX + rowA]) : SENT;
    unsigned qa7 = (cntA > 7) ? __ldg(&g_rb[7 * NMAX + rowA]) : SENT;
    unsigned qb0 = (cntB > 0) ? __ldg(&g_rb[0 * NMAX + rowB]) : SENT;
    unsigned qb1 = (cntB > 1) ? __ldg(&g_rb[1 * NMAX + rowB]) : SENT;
    unsigned qb2 = (cntB > 2) ? __ldg(&g_rb[2 * NMAX + rowB]) : SENT;
    unsigned qb3 = (cntB > 3) ? __ldg(&g_rb[3 * NMAX + rowB]) : SENT;
    unsigned qb4 = (cntB > 4) ? __ldg(&g_rb[4 * NMAX + rowB]) : SENT;
    unsigned qb5 = (cntB > 5) ? __ldg(&g_rb[5 * NMAX + rowB]) : SENT;
    unsigned qb6 = (cntB > 6) ? __ldg(&g_rb[6 * NMAX + rowB]) : SENT;
    unsigned qb7 = (cntB > 7) ? __ldg(&g_rb[7 * NMAX + rowB]) : SENT;
    int eA = 8, eB = 8;

    if (qa0 != SENT) prefetchL1(&f14[(qa0 & 0x7FFFF) * 8]);
    if (qa1 != SENT) prefetchL1(&f14[(qa1 & 0x7FFFF) * 8]);
    if (qb0 != SENT) prefetchL1(&f14[(qb0 & 0x7FFFF) * 8]);
    if (qb1 != SENT) prefetchL1(&f14[(qb1 & 0x7FFFF) * 8]);

    int swz = (lane & 7) * 4;

    #pragma unroll 1
    for (int k = 0; k < 27; k++) {
        bool tA = ((qa0 >> 19) == (unsigned)k);
        bool tB = ((qb0 >> 19) == (unsigned)k);
        unsigned maskA = __ballot_sync(FULLW, tA);
        unsigned maskB = __ballot_sync(FULLW, tB);
        if (maskA | maskB) {
            const float* wrow = &smw[(k * 32 + lane) * 32];
            float4 w0 = *(const float4*)&wrow[(0 * 4) ^ swz];
            float4 w1 = *(const float4*)&wrow[(1 * 4) ^ swz];
            float4 w2 = *(const float4*)&wrow[(2 * 4) ^ swz];
            float4 w3 = *(const float4*)&wrow[(3 * 4) ^ swz];
            float4 w4 = *(const float4*)&wrow[(4 * 4) ^ swz];
            float4 w5 = *(const float4*)&wrow[(5 * 4) ^ swz];
            float4 w6 = *(const float4*)&wrow[(6 * 4) ^ swz];
            float4 w7 = *(const float4*)&wrow[(7 * 4) ^ swz];
            // process both row sets with the same register weights
            #pragma unroll 1
            for (int set = 0; set < 2; set++) {
                unsigned mm = set ? maskB : maskA;
                unsigned qh = set ? qb0 : qa0;
                int rbase = set ? 32 : 0;
                #pragma unroll 1
                while (mm) {
                    int j0 = __ffs(mm) - 1; mm &= mm - 1;
                    int j1 = -1;
                    if (mm) { j1 = __ffs(mm) - 1; mm &= mm - 1; }
                    int i0 = __shfl_sync(FULLW, (int)qh, j0) & 0x7FFFF;
                    int i1 = __shfl_sync(FULLW, (int)qh, (j1 >= 0) ? j1 : j0) & 0x7FFFF;
                    const float4* fp0 = &f14[i0 * 8];
                    const float4* fp1 = &f14[i1 * 8];
                    float4 a0 = __ldg(fp0 + 0), a1 = __ldg(fp0 + 1);
                    float4 a2 = __ldg(fp0 + 2), a3 = __ldg(fp0 + 3);
                    float4 a4 = __ldg(fp0 + 4), a5 = __ldg(fp0 + 5);
                    float4 a6 = __ldg(fp0 + 6), a7 = __ldg(fp0 + 7);
                    float4 b0, b1_, b2, b3, b4, b5, b6, b7;
                    if (j1 >= 0) {
                        b0 = __ldg(fp1 + 0); b1_ = __ldg(fp1 + 1);
                        b2 = __ldg(fp1 + 2); b3 = __ldg(fp1 + 3);
                        b4 = __ldg(fp1 + 4); b5 = __ldg(fp1 + 5);
                        b6 = __ldg(fp1 + 6); b7 = __ldg(fp1 + 7);
                    }
                    float r0 = 0.f;
                    r0 = fmaf(a0.x, w0.x, r0); r0 = fmaf(a0.y, w0.y, r0);
                    r0 = fmaf(a0.z, w0.z, r0); r0 = fmaf(a0.w, w0.w, r0);
                    r0 = fmaf(a1.x, w1.x, r0); r0 = fmaf(a1.y, w1.y, r0);
                    r0 = fmaf(a1.z, w1.z, r0); r0 = fmaf(a1.w, w1.w, r0);
                    r0 = fmaf(a2.x, w2.x, r0); r0 = fmaf(a2.y, w2.y, r0);
                    r0 = fmaf(a2.z, w2.z, r0); r0 = fmaf(a2.w, w2.w, r0);
                    r0 = fmaf(a3.x, w3.x, r0); r0 = fmaf(a3.y, w3.y, r0);
                    r0 = fmaf(a3.z, w3.z, r0); r0 = fmaf(a3.w, w3.w, r0);
                    r0 = fmaf(a4.x, w4.x, r0); r0 = fmaf(a4.y, w4.y, r0);
                    r0 = fmaf(a4.z, w4.z, r0); r0 = fmaf(a4.w, w4.w, r0);
                    r0 = fmaf(a5.x, w5.x, r0); r0 = fmaf(a5.y, w5.y, r0);
                    r0 = fmaf(a5.z, w5.z, r0); r0 = fmaf(a5.w, w5.w, r0);
                    r0 = fmaf(a6.x, w6.x, r0); r0 = fmaf(a6.y, w6.y, r0);
                    r0 = fmaf(a6.z, w6.z, r0); r0 = fmaf(a6.w, w6.w, r0);
                    r0 = fmaf(a7.x, w7.x, r0); r0 = fmaf(a7.y, w7.y, r0);
                    r0 = fmaf(a7.z, w7.z, r0); r0 = fmaf(a7.w, w7.w, r0);
                    sacc[(rbase + j0) * 32 + lane] += r0;
                    if (j1 >= 0) {
                        float r1 = 0.f;
                        r1 = fmaf(b0.x, w0.x, r1); r1 = fmaf(b0.y, w0.y, r1);
                        r1 = fmaf(b0.z, w0.z, r1); r1 = fmaf(b0.w, w0.w, r1);
                        r1 = fmaf(b1_.x, w1.x, r1); r1 = fmaf(b1_.y, w1.y, r1);
                        r1 = fmaf(b1_.z, w1.z, r1); r1 = fmaf(b1_.w, w1.w, r1);
                        r1 = fmaf(b2.x, w2.x, r1); r1 = fmaf(b2.y, w2.y, r1);
                        r1 = fmaf(b2.z, w2.z, r1); r1 = fmaf(b2.w, w2.w, r1);
                        r1 = fmaf(b3.x, w3.x, r1); r1 = fmaf(b3.y, w3.y, r1);
                        r1 = fmaf(b3.z, w3.z, r1); r1 = fmaf(b3.w, w3.w, r1);
                        r1 = fmaf(b4.x, w4.x, r1); r1 = fmaf(b4.y, w4.y, r1);
                        r1 = fmaf(b4.z, w4.z, r1); r1 = fmaf(b4.w, w4.w, r1);
                        r1 = fmaf(b5.x, w5.x, r1); r1 = fmaf(b5.y, w5.y, r1);
                        r1 = fmaf(b5.z, w5.z, r1); r1 = fmaf(b5.w, w5.w, r1);
                        r1 = fmaf(b6.x, w6.x, r1); r1 = fmaf(b6.y, w6.y, r1);
                        r1 = fmaf(b6.z, w6.z, r1); r1 = fmaf(b6.w, w6.w, r1);
                        r1 = fmaf(b7.x, w7.x, r1); r1 = fmaf(b7.y, w7.y, r1);
                        r1 = fmaf(b7.z, w7.z, r1); r1 = fmaf(b7.w, w7.w, r1);
                        sacc[(rbase + j1) * 32 + lane] += r1;
                    }
                }
            }
        }
        if (tA) {
            qa0 = qa1; qa1 = qa2; qa2 = qa3; qa3 = qa4;
            qa4 = qa5; qa5 = qa6; qa6 = qa7;
            qa7 = (eA < cntA) ? __ldg(&g_rb[eA * NMAX + rowA]) : SENT;
            eA++;
            if (qa1 != SENT) prefetchL1(&f14[(qa1 & 0x7FFFF) * 8]);
        }
        if (tB) {
            qb0 = qb1; qb1 = qb2; qb2 = qb3; qb3 = qb4;
            qb4 = qb5; qb5 = qb6; qb6 = qb7;
            qb7 = (eB < cntB) ? __ldg(&g_rb[eB * NMAX + rowB]) : SENT;
            eB++;
            if (qb1 != SENT) prefetchL1(&f14[(qb1 & 0x7FFFF) * 8]);
        }
    }

    int co = half * 32 + lane;
    float s  = g2[co] * rsqrtf(v2[co] + BN_EPS);
    float sh = b2[co] - m2[co] * s;
    #pragma unroll
    for (int r = 0; r < 64; r++) {
        int rr = base + r;
        if (rr < m) {
            float o = fmaf(sacc[r * 32 + lane], s, sh);
            out[rr * C2 + co] = o > 0.f ? o : 0.f;
        }
    }
}

// ---------------------------------------------------------------------------
// Tail: fill everything past f2 (out_coors as float, batch_size) if the
// harness flattened the full reference tuple into d_out.
// ---------------------------------------------------------------------------
__global__ void tail_kernel(const int* __restrict__ ocoors,
                            const int* __restrict__ bsz,
                            float* __restrict__ out, int m, int total)
{
    int i = blockIdx.x * blockDim.x + threadIdx.x + m * 64;
    if (i >= total) return;
    int j = i - m * 64;
    float v;
    if (j < m * 4)       v = (float)ocoors[j];
    else if (j == m * 4) v = (float)bsz[0];
    else                 v = 0.f;
    out[i] = v;
}

// ---------------------------------------------------------------------------
extern "C" void kernel_launch(void* const* d_in, const int* in_sizes, int n_in,
                              void* d_out, int out_size)
{
    const float* feat   = (const float*)d_in[0];
    const int*   coors  = (const int*)d_in[1];
    const int*   ocoors = (const int*)d_in[2];
    const float* W1     = (const float*)d_in[3];
    const float* g1     = (const float*)d_in[4];
    const float* b1     = (const float*)d_in[5];
    const float* m1     = (const float*)d_in[6];
    const float* v1     = (const float*)d_in[7];
    const float* W2     = (const float*)d_in[8];
    const float* g2     = (const float*)d_in[9];
    const float* b2     = (const float*)d_in[10];
    const float* m2     = (const float*)d_in[11];
    const float* v2     = (const float*)d_in[12];
    const int*   bsz    = (const int*)d_in[13];

    int n = in_sizes[0] / CIN;
    int m = in_sizes[2] / 4;

    fill_grid_kernel<<<(GRID_SZ / 4 + 255) / 256, 256>>>();
    scatter_kernel<<<(n + 255) / 256, 256>>>(coors, n);

    // layer 1 (R10 form: inline probes, register acc, 2 blocks/SM)
    int smem1 = 27 * C1 * 32 * (int)sizeof(float);   // 110,592 B
    cudaFuncSetAttribute(conv1_kernel, cudaFuncAttributeMaxDynamicSharedMemorySize, smem1);
    conv1_kernel<<<(n + 255) / 256, 512, smem1>>>(feat, coors, W1, g1, b1, m1, v1, n);

    // layer 2: rulebook, then conv with dual-queue 64-rows-per-warp
    rb2_build_kernel<<<(m + 255) / 256, 256>>>(ocoors, m);
    int smem2 = (CONV2_W_ELEMS + 12 * 64 * 32) * (int)sizeof(float);   // 206,848 B
    cudaFuncSetAttribute(conv2_kernel, cudaFuncAttributeMaxDynamicSharedMemorySize, smem2);
    int rowblocks = (m + 767) / 768;
    conv2_kernel<<<rowblocks * 2, 384, smem2>>>(W2, g2, b2, m2, v2, (float*)d_out, m);

    int tail = out_size - m * 64;
    if (tail > 0) {
        tail_kernel<<<(tail + 255) / 256, 256>>>(ocoors, bsz, (float*)d_out, m, out_size);
    }
}

// round 16
// speedup vs baseline: 1.0439x; 1.0437x over previous
#include <cuda_runtime.h>
#include <cuda_bf16.h>

#define ZD 21
#define YD 256
#define XD 256
#define CIN 16
#define C1 32
#define C2 64
#define BN_EPS 1e-3f
#define GRID_SZ (2 * ZD * YD * XD)   // 2,752,512
#define NMAX 400000
#define FULLW 0xffffffffu
#define ROWVALID 64        // mask bit: this row exists
#define SENT 0xffffffffu   // queue sentinel: k-field = 8191, never matches

__device__ int      g_grid[GRID_SZ];
__device__ float    g_f1[NMAX * C1];
__device__ unsigned g_rb[27 * NMAX];   // slot-major: rb[e*NMAX + row] (layer-2 only)
__device__ int      g_cnt[NMAX];

__device__ __forceinline__ void prefetchL1(const void* p) {
    asm volatile("prefetch.global.L1 [%0];" :: "l"(p));
}

// ---------------------------------------------------------------------------
// Hash-grid build
// ---------------------------------------------------------------------------
__global__ void fill_grid_kernel() {
    int i = blockIdx.x * blockDim.x + threadIdx.x;
    if (i < GRID_SZ / 4) {
        ((int4*)g_grid)[i] = make_int4(-1, -1, -1, -1);
    }
}

__global__ void scatter_kernel(const int* __restrict__ coors, int n) {
    int i = blockIdx.x * blockDim.x + threadIdx.x;
    if (i < n) {
        int4 c = ((const int4*)coors)[i];  // (b, z, y, x)
        int lin = ((c.x * ZD + c.y) * YD + c.z) * XD + c.w;
        g_grid[lin] = i;
    }
}

// ---------------------------------------------------------------------------
// Probe helpers
// ---------------------------------------------------------------------------
__device__ __forceinline__ int probe2(int k, int lin, int msk) {
    int jz = k / 9, jy = (k / 3) % 3, jx = k % 3;
    int req = ((jy == 0) ? 1 : 0) | ((jx == 0) ? 2 : 0) | ROWVALID;
    int koff = (jz * YD + jy) * XD + jx;
    return ((msk & req) == req) ? __ldg(&g_grid[lin + koff]) : -1;
}

// ---------------------------------------------------------------------------
// Layer-2 rulebook: one thread per output row; 27 independent probes, then
// compact k-ascending entries (k<<19 | irow) into slot-major g_rb.
// ---------------------------------------------------------------------------
__global__ void rb2_build_kernel(const int* __restrict__ ocoors, int m) {
    int row = blockIdx.x * blockDim.x + threadIdx.x;
    if (row >= m) return;
    int4 c = ((const int4*)ocoors)[row];  // (b, oz, oy, ox)
    int z0 = c.y * 2;
    int y0 = c.z * 2 - 1;
    int x0 = c.w * 2 - 1;
    int lin = ((c.x * ZD + z0) * YD + y0) * XD + x0;   // may be < 0; probes guard
    int msk = (c.z > 0) | ((c.w > 0) << 1) | ROWVALID;
    int idx[27];
    #pragma unroll
    for (int k = 0; k < 27; k++) idx[k] = probe2(k, lin, msk);
    int cnt = 0;
    #pragma unroll
    for (int k = 0; k < 27; k++) {
        if (idx[k] >= 0) g_rb[(cnt++) * NMAX + row] = ((unsigned)k << 19) | (unsigned)idx[k];
    }
    g_cnt[row] = cnt;
}

extern __shared__ float smw[];

#define CONV2_W_ELEMS (27 * 32 * 32)

// ---------------------------------------------------------------------------
// Layer 1: SubMConv3d k=3 pad=1, CIN=16 -> C1=32, fused BN+ReLU
// 512 thr = 16 warps, 2 blocks/SM. Warp owns 16 rows, lane = cout.
// k-outer, per-k register weights, depth-1 probe prefetch with the probe
// CONSUMED ONLY AFTER the current k's compute (probe latency hidden behind
// the mask/FMA work instead of exposed by an early guarded prefetch).
// ---------------------------------------------------------------------------
__global__ __launch_bounds__(512, 2) void conv1_kernel(
    const float* __restrict__ feat, const int* __restrict__ coors,
    const float* __restrict__ W1,
    const float* __restrict__ g1, const float* __restrict__ b1,
    const float* __restrict__ m1, const float* __restrict__ v1,
    int n)
{
    for (int e = threadIdx.x; e < 27 * CIN * C1; e += blockDim.x) {
        int k   = e / (CIN * C1);
        int rem = e % (CIN * C1);
        int ci  = rem / C1;
        int co  = rem % C1;
        int chunk = ci >> 2, pos = ci & 3;
        int sch = chunk ^ (co & 7);
        smw[(k * 32 + co) * 32 + sch * 4 + pos] = W1[e];
    }
    __syncthreads();

    int warp = threadIdx.x >> 5;
    int lane = threadIdx.x & 31;
    int row0 = blockIdx.x * 256 + warp * 16;

    int lin = 0, msk = 0;
    if (lane < 16) {
        int r = row0 + lane;
        if (r < n) {
            int4 c = ((const int4*)coors)[r];  // (b, z, y, x)
            lin = ((c.x * ZD + c.y) * YD + c.z) * XD + c.w;
            msk = (c.y > 0)             |
                  ((c.y < ZD - 1) << 1) |
                  ((c.z > 0)      << 2) |
                  ((c.z < YD - 1) << 3) |
                  ((c.w > 0)      << 4) |
                  ((c.w < XD - 1) << 5) |
                  ROWVALID;
        }
    }

    float acc[16];
    #pragma unroll
    for (int r = 0; r < 16; r++) acc[r] = 0.f;

    const float4* feat4 = (const float4*)feat;
    int swz = (lane & 7) * 4;

    // prime: issue probe for k=0; don't touch its value until the loop body
    int cur;
    {
        int req = 1 | 4 | 16 | ROWVALID;              // k=0: dz,dy,dx = -1
        int koff = (-1 * YD - 1) * XD - 1;
        cur = ((msk & req) == req) ? __ldg(&g_grid[lin + koff]) : -1;
    }
    int k = 0;
    #pragma unroll 1
    for (int dz = -1; dz <= 1; dz++) {
        #pragma unroll 1
        for (int dy = -1; dy <= 1; dy++) {
            #pragma unroll 1
            for (int dx = -1; dx <= 1; dx++, k++) {
                // 1) ISSUE next probe load (value not consumed yet)
                int nxt = -1;
                if (k < 26) {
                    int k1 = k + 1;
                    int dz1 = k1 / 9 - 1, dy1 = (k1 / 3) % 3 - 1, dx1 = k1 % 3 - 1;
                    int req1 = ((dz1 < 0) ? 1 : 0) | ((dz1 > 0) ? 2 : 0) |
                               ((dy1 < 0) ? 4 : 0) | ((dy1 > 0) ? 8 : 0) |
                               ((dx1 < 0) ? 16 : 0) | ((dx1 > 0) ? 32 : 0) | ROWVALID;
                    int koff1 = (dz1 * YD + dy1) * XD + dx1;
                    nxt = ((msk & req1) == req1) ? __ldg(&g_grid[lin + koff1]) : -1;
                }
                // 2) compute current k (hundreds of cycles; probe load in flight)
                unsigned mask = __ballot_sync(FULLW, cur >= 0) & 0xffffu;
                if (mask) {
                    const float* wrow = &smw[(k * 32 + lane) * 32];
                    float4 w0 = *(const float4*)&wrow[(0 * 4) ^ swz];
                    float4 w1 = *(const float4*)&wrow[(1 * 4) ^ swz];
                    float4 w2 = *(const float4*)&wrow[(2 * 4) ^ swz];
                    float4 w3 = *(const float4*)&wrow[(3 * 4) ^ swz];
                    #pragma unroll
                    for (int r = 0; r < 16; r++) {
                        if ((mask >> r) & 1) {   // warp-uniform
                            int idx = __shfl_sync(FULLW, cur, r);
                            const float4* fp = &feat4[idx * 4];
                            float4 f0 = __ldg(fp + 0);
                            float4 f1 = __ldg(fp + 1);
                            float4 f2 = __ldg(fp + 2);
                            float4 f3 = __ldg(fp + 3);
                            float a = acc[r];
                            a = fmaf(f0.x, w0.x, a); a = fmaf(f0.y, w0.y, a);
                            a = fmaf(f0.z, w0.z, a); a = fmaf(f0.w, w0.w, a);
                            a = fmaf(f1.x, w1.x, a); a = fmaf(f1.y, w1.y, a);
                            a = fmaf(f1.z, w1.z, a); a = fmaf(f1.w, w1.w, a);
                            a = fmaf(f2.x, w2.x, a); a = fmaf(f2.y, w2.y, a);
                            a = fmaf(f2.z, w2.z, a); a = fmaf(f2.w, w2.w, a);
                            a = fmaf(f3.x, w3.x, a); a = fmaf(f3.y, w3.y, a);
                            a = fmaf(f3.z, w3.z, a); a = fmaf(f3.w, w3.w, a);
                            acc[r] = a;
                        }
                    }
                }
                // 3) NOW consume the probe value: warm its feature line
                if (nxt >= 0) prefetchL1(&feat4[nxt * 4]);
                cur = nxt;
            }
        }
    }

    float s  = g1[lane] * rsqrtf(v1[lane] + BN_EPS);
    float sh = b1[lane] - m1[lane] * s;
    #pragma unroll
    for (int r = 0; r < 16; r++) {
        int row = row0 + r;
        if (row < n) {
            float o = fmaf(acc[r], s, sh);
            g_f1[row * C1 + lane] = o > 0.f ? o : 0.f;
        }
    }
}

// ---------------------------------------------------------------------------
// Layer 2: SparseConv3d C1=32 -> C2=64, fused BN+ReLU.
// (exact R10 measured-best form.) Cout halves split ACROSS BLOCKS.
// 512 thr = 16 warps, 1 block/SM (smem = 110.6KB weights + 64KB smem acc).
// Warp owns 32 rows (one per lane); lane = local cout. SMEM accumulators +
// 2-way-interleaved __ffs pair loop; 8-deep queue, depth-2 feature prefetch.
// ---------------------------------------------------------------------------
__global__ __launch_bounds__(512, 1) void conv2_kernel(
    const float* __restrict__ W2,
    const float* __restrict__ g2, const float* __restrict__ b2,
    const float* __restrict__ m2, const float* __restrict__ v2,
    float* __restrict__ out, int m)
{
    int half = blockIdx.x & 1;

    for (int e = threadIdx.x; e < CONV2_W_ELEMS; e += blockDim.x) {
        int k   = e / (C1 * 32);
        int rem = e % (C1 * 32);
        int ci  = rem / 32;
        int col = rem % 32;
        int chunk = ci >> 2, pos = ci & 3;
        int sch = chunk ^ (col & 7);
        smw[(k * 32 + col) * 32 + sch * 4 + pos] =
            W2[(k * C1 + ci) * C2 + half * 32 + col];
    }

    int warp = threadIdx.x >> 5;
    int lane = threadIdx.x & 31;

    float* sacc = smw + CONV2_W_ELEMS + warp * (32 * 32);
    #pragma unroll
    for (int r = 0; r < 32; r++) sacc[r * 32 + lane] = 0.f;
    __syncthreads();

    int row0 = (blockIdx.x >> 1) * 512 + warp * 32;
    int row  = row0 + lane;

    const float4* f14 = (const float4*)g_f1;

    int cnt = (row < m) ? __ldg(&g_cnt[row]) : 0;
    unsigned q0 = (cnt > 0) ? __ldg(&g_rb[0 * NMAX + row]) : SENT;
    unsigned q1 = (cnt > 1) ? __ldg(&g_rb[1 * NMAX + row]) : SENT;
    unsigned q2 = (cnt > 2) ? __ldg(&g_rb[2 * NMAX + row]) : SENT;
    unsigned q3 = (cnt > 3) ? __ldg(&g_rb[3 * NMAX + row]) : SENT;
    unsigned q4 = (cnt > 4) ? __ldg(&g_rb[4 * NMAX + row]) : SENT;
    unsigned q5 = (cnt > 5) ? __ldg(&g_rb[5 * NMAX + row]) : SENT;
    unsigned q6 = (cnt > 6) ? __ldg(&g_rb[6 * NMAX + row]) : SENT;
    unsigned q7 = (cnt > 7) ? __ldg(&g_rb[7 * NMAX + row]) : SENT;
    int e = 8;

    if (q0 != SENT) prefetchL1(&f14[(q0 & 0x7FFFF) * 8]);
    if (q1 != SENT) prefetchL1(&f14[(q1 & 0x7FFFF) * 8]);

    int swz = (lane & 7) * 4;

    #pragma unroll 1
    for (int k = 0; k < 27; k++) {
        bool take = ((q0 >> 19) == (unsigned)k);
        unsigned mask = __ballot_sync(FULLW, take);
        if (mask) {
            const float* wrow = &smw[(k * 32 + lane) * 32];
            float4 w0 = *(const float4*)&wrow[(0 * 4) ^ swz];
            float4 w1 = *(const float4*)&wrow[(1 * 4) ^ swz];
            float4 w2 = *(const float4*)&wrow[(2 * 4) ^ swz];
            float4 w3 = *(const float4*)&wrow[(3 * 4) ^ swz];
            float4 w4 = *(const float4*)&wrow[(4 * 4) ^ swz];
            float4 w5 = *(const float4*)&wrow[(5 * 4) ^ swz];
            float4 w6 = *(const float4*)&wrow[(6 * 4) ^ swz];
            float4 w7 = *(const float4*)&wrow[(7 * 4) ^ swz];
            unsigned mm = mask;
            #pragma unroll 1
            while (mm) {
                int j0 = __ffs(mm) - 1; mm &= mm - 1;
                int j1 = -1;
                if (mm) { j1 = __ffs(mm) - 1; mm &= mm - 1; }
                int i0 = __shfl_sync(FULLW, (int)q0, j0) & 0x7FFFF;
                int i1 = __shfl_sync(FULLW, (int)q0, (j1 >= 0) ? j1 : j0) & 0x7FFFF;
                const float4* fp0 = &f14[i0 * 8];
                const float4* fp1 = &f14[i1 * 8];
                // issue BOTH pairs' loads before either chain
                float4 a0 = __ldg(fp0 + 0), a1 = __ldg(fp0 + 1);
                float4 a2 = __ldg(fp0 + 2), a3 = __ldg(fp0 + 3);
                float4 a4 = __ldg(fp0 + 4), a5 = __ldg(fp0 + 5);
                float4 a6 = __ldg(fp0 + 6), a7 = __ldg(fp0 + 7);
                float4 b0, b1_, b2, b3, b4, b5, b6, b7;
                if (j1 >= 0) {
                    b0 = __ldg(fp1 + 0); b1_ = __ldg(fp1 + 1);
                    b2 = __ldg(fp1 + 2); b3 = __ldg(fp1 + 3);
                    b4 = __ldg(fp1 + 4); b5 = __ldg(fp1 + 5);
                    b6 = __ldg(fp1 + 6); b7 = __ldg(fp1 + 7);
                }
                float r0 = 0.f;
                r0 = fmaf(a0.x, w0.x, r0); r0 = fmaf(a0.y, w0.y, r0);
                r0 = fmaf(a0.z, w0.z, r0); r0 = fmaf(a0.w, w0.w, r0);
                r0 = fmaf(a1.x, w1.x, r0); r0 = fmaf(a1.y, w1.y, r0);
                r0 = fmaf(a1.z, w1.z, r0); r0 = fmaf(a1.w, w1.w, r0);
                r0 = fmaf(a2.x, w2.x, r0); r0 = fmaf(a2.y, w2.y, r0);
                r0 = fmaf(a2.z, w2.z, r0); r0 = fmaf(a2.w, w2.w, r0);
                r0 = fmaf(a3.x, w3.x, r0); r0 = fmaf(a3.y, w3.y, r0);
                r0 = fmaf(a3.z, w3.z, r0); r0 = fmaf(a3.w, w3.w, r0);
                r0 = fmaf(a4.x, w4.x, r0); r0 = fmaf(a4.y, w4.y, r0);
                r0 = fmaf(a4.z, w4.z, r0); r0 = fmaf(a4.w, w4.w, r0);
                r0 = fmaf(a5.x, w5.x, r0); r0 = fmaf(a5.y, w5.y, r0);
                r0 = fmaf(a5.z, w5.z, r0); r0 = fmaf(a5.w, w5.w, r0);
                r0 = fmaf(a6.x, w6.x, r0); r0 = fmaf(a6.y, w6.y, r0);
                r0 = fmaf(a6.z, w6.z, r0); r0 = fmaf(a6.w, w6.w, r0);
                r0 = fmaf(a7.x, w7.x, r0); r0 = fmaf(a7.y, w7.y, r0);
                r0 = fmaf(a7.z, w7.z, r0); r0 = fmaf(a7.w, w7.w, r0);
                sacc[j0 * 32 + lane] += r0;
                if (j1 >= 0) {
                    float r1 = 0.f;
                    r1 = fmaf(b0.x, w0.x, r1); r1 = fmaf(b0.y, w0.y, r1);
                    r1 = fmaf(b0.z, w0.z, r1); r1 = fmaf(b0.w, w0.w, r1);
                    r1 = fmaf(b1_.x, w1.x, r1); r1 = fmaf(b1_.y, w1.y, r1);
                    r1 = fmaf(b1_.z, w1.z, r1); r1 = fmaf(b1_.w, w1.w, r1);
                    r1 = fmaf(b2.x, w2.x, r1); r1 = fmaf(b2.y, w2.y, r1);
                    r1 = fmaf(b2.z, w2.z, r1); r1 = fmaf(b2.w, w2.w, r1);
                    r1 = fmaf(b3.x, w3.x, r1); r1 = fmaf(b3.y, w3.y, r1);
                    r1 = fmaf(b3.z, w3.z, r1); r1 = fmaf(b3.w, w3.w, r1);
                    r1 = fmaf(b4.x, w4.x, r1); r1 = fmaf(b4.y, w4.y, r1);
                    r1 = fmaf(b4.z, w4.z, r1); r1 = fmaf(b4.w, w4.w, r1);
                    r1 = fmaf(b5.x, w5.x, r1); r1 = fmaf(b5.y, w5.y, r1);
                    r1 = fmaf(b5.z, w5.z, r1); r1 = fmaf(b5.w, w5.w, r1);
                    r1 = fmaf(b6.x, w6.x, r1); r1 = fmaf(b6.y, w6.y, r1);
                    r1 = fmaf(b6.z, w6.z, r1); r1 = fmaf(b6.w, w6.w, r1);
                    r1 = fmaf(b7.x, w7.x, r1); r1 = fmaf(b7.y, w7.y, r1);
                    r1 = fmaf(b7.z, w7.z, r1); r1 = fmaf(b7.w, w7.w, r1);
                    sacc[j1 * 32 + lane] += r1;
                }
            }
        }
        if (take) {   // static shift-register consume; lazy tail refill
            q0 = q1; q1 = q2; q2 = q3; q3 = q4;
            q4 = q5; q5 = q6; q6 = q7;
            q7 = (e < cnt) ? __ldg(&g_rb[e * NMAX + row]) : SENT;
            e++;
            if (q1 != SENT) prefetchL1(&f14[(q1 & 0x7FFFF) * 8]);
        }
    }

    int co = half * 32 + lane;
    float s  = g2[co] * rsqrtf(v2[co] + BN_EPS);
    float sh = b2[co] - m2[co] * s;
    #pragma unroll
    for (int r = 0; r < 32; r++) {
        int rr = row0 + r;
        if (rr < m) {
            float o = fmaf(sacc[r * 32 + lane], s, sh);
            out[rr * C2 + co] = o > 0.f ? o : 0.f;
        }
    }
}

// ---------------------------------------------------------------------------
// Tail: fill everything past f2 (out_coors as float, batch_size) if the
// harness flattened the full reference tuple into d_out.
// ---------------------------------------------------------------------------
__global__ void tail_kernel(const int* __restrict__ ocoors,
                            const int* __restrict__ bsz,
                            float* __restrict__ out, int m, int total)
{
    int i = blockIdx.x * blockDim.x + threadIdx.x + m * 64;
    if (i >= total) return;
    int j = i - m * 64;
    float v;
    if (j < m * 4)       v = (float)ocoors[j];
    else if (j == m * 4) v = (float)bsz[0];
    else                 v = 0.f;
    out[i] = v;
}

// ---------------------------------------------------------------------------
extern "C" void kernel_launch(void* const* d_in, const int* in_sizes, int n_in,
                              void* d_out, int out_size)
{
    const float* feat   = (const float*)d_in[0];
    const int*   coors  = (const int*)d_in[1];
    const int*   ocoors = (const int*)d_in[2];
    const float* W1     = (const float*)d_in[3];
    const float* g1     = (const float*)d_in[4];
    const float* b1     = (const float*)d_in[5];
    const float* m1     = (const float*)d_in[6];
    const float* v1     = (const float*)d_in[7];
    const float* W2     = (const float*)d_in[8];
    const float* g2     = (const float*)d_in[9];
    const float* b2     = (const float*)d_in[10];
    const float* m2     = (const float*)d_in[11];
    const float* v2     = (const float*)d_in[12];
    const int*   bsz    = (const int*)d_in[13];

    int n = in_sizes[0] / CIN;
    int m = in_sizes[2] / 4;

    fill_grid_kernel<<<(GRID_SZ / 4 + 255) / 256, 256>>>();
    scatter_kernel<<<(n + 255) / 256, 256>>>(coors, n);

    // layer 1 (R10 form + probe/compute reorder)
    int smem1 = 27 * C1 * 32 * (int)sizeof(float);   // 110,592 B
    cudaFuncSetAttribute(conv1_kernel, cudaFuncAttributeMaxDynamicSharedMemorySize, smem1);
    conv1_kernel<<<(n + 255) / 256, 512, smem1>>>(feat, coors, W1, g1, b1, m1, v1, n);

    // layer 2: rulebook, then conv with smem accumulators + pipelined pair loop
    rb2_build_kernel<<<(m + 255) / 256, 256>>>(ocoors, m);
    int smem2 = (CONV2_W_ELEMS + 16 * 32 * 32) * (int)sizeof(float);   // 176,128 B
    cudaFuncSetAttribute(conv2_kernel, cudaFuncAttributeMaxDynamicSharedMemorySize, smem2);
    int rowblocks = (m + 511) / 512;
    conv2_kernel<<<rowblocks * 2, 512, smem2>>>(W2, g2, b2, m2, v2, (float*)d_out, m);

    int tail = out_size - m * 64;
    if (tail > 0) {
        tail_kernel<<<(tail + 255) / 256, 256>>>(ocoors, bsz, (float*)d_out, m, out_size);
    }
}